// round 2
// baseline (speedup 1.0000x reference)
#include <cuda_runtime.h>
#include <cuda_fp16.h>
#include <cstdint>

#define NPOS 1008
#define NTAU 752
#define NCH  256
#define NM   9
#define TB   8
#define NCAP 288

// ---------------- device globals (scratch) ----------------
__device__ float   g_wav[128 * 512];      // wav[o*512 + k]
__device__ __half  g_Ehf[1264 * 256];     // padded E^T: row (tau+256), col c  (fp16)
__device__ __half  g_Whf[147456];         // W_caps in fp16

// ---------------- packed fp32x2 helpers ----------------
static __device__ __forceinline__ unsigned long long ffma2(unsigned long long a,
                                                           unsigned long long b,
                                                           unsigned long long c) {
    unsigned long long d;
    asm("fma.rn.f32x2 %0, %1, %2, %3;" : "=l"(d) : "l"(a), "l"(b), "l"(c));
    return d;
}
static __device__ __forceinline__ unsigned long long bcast2(float e) {
    unsigned long long d;
    unsigned int u = __float_as_uint(e);
    asm("mov.b64 %0, {%1, %1};" : "=l"(d) : "r"(u));
    return d;
}
static __device__ __forceinline__ float2 unpack2(unsigned long long v) {
    unsigned int lo, hi;
    asm("mov.b64 {%0, %1}, %2;" : "=r"(lo), "=r"(hi) : "l"(v));
    float2 r; r.x = __uint_as_float(lo); r.y = __uint_as_float(hi);
    return r;
}

// ---------------- kernel A: wavelet weights ----------------
__global__ void wav_kernel(const float* __restrict__ a, const float* __restrict__ w) {
    int o = blockIdx.x;          // 0..127
    int k = threadIdx.x;         // 0..511
    float av = fmaxf(a[o], 1e-5f);
    float wv = w[o];
    float t  = fmaf((float)k, 2.0f / 511.0f, -1.0f);
    float ts = t / av;
    g_wav[o * 512 + k] = cosf(wv * t) * expf(-0.5f * ts * ts);
}

// ---------------- kernel P: zero the pad rows of E (deterministic) ----------------
__global__ void pad_kernel() {
    int idx = blockIdx.x * blockDim.x + threadIdx.x;    // 512*256 = 131072 elems
    if (idx < 512 * 256) {
        int row = idx >> 8;                 // 0..511
        int col = idx & 255;
        int r = (row < 256) ? row : (row + 752);        // [0,256) and [1008,1264)
        g_Ehf[r * 256 + col] = __float2half_rn(0.0f);
    }
}

// ---------------- kernel B: compose E[c,tau] = sum_{k2,o} conv_w[c,o,k2]*wav[o,tau-16k2] ----------------
__global__ void compose_kernel(const float* __restrict__ conv_w) {
    __shared__ float cw[2048];              // conv_w[c][o][k2] : o*16 + k2
    int c = blockIdx.x;                     // 0..255
    for (int i = threadIdx.x; i < 2048; i += blockDim.x)
        cw[i] = conv_w[c * 2048 + i];
    __syncthreads();
    for (int tau = threadIdx.x; tau < NTAU; tau += blockDim.x) {
        float acc = 0.0f;
        #pragma unroll
        for (int k2 = 0; k2 < 16; ++k2) {
            int k = tau - 16 * k2;
            if (k >= 0 && k < 512) {
                const float* wr = g_wav + k;
                #pragma unroll 8
                for (int o = 0; o < 128; ++o)
                    acc = fmaf(cw[o * 16 + k2], wr[o * 512], acc);
            }
        }
        g_Ehf[(tau + 256) * 256 + c] = __float2half_rn(acc);
    }
}

// ---------------- kernel D: W_caps -> fp16 ----------------
__global__ void wbf_kernel(const float* __restrict__ Wc) {
    int i = blockIdx.x * blockDim.x + threadIdx.x;
    if (i < 147456) g_Whf[i] = __float2half_rn(Wc[i]);
}

// ---------------- main fused kernel ----------------
// smem layout (floats):
//   ps   : TB*2304        = 18432
//   reg1 : max(xs 8064, uh 288*65=18720) = 18720
//   bij 1152, cij 1152, part 256, sj 64, vv 64, snd 4  => 2692
#define SMEM_FLOATS (18432 + 18720 + 2692)
#define SMEM_BYTES  (SMEM_FLOATS * 4)

__global__ __launch_bounds__(256, 1)
void fused_kernel(const float* __restrict__ x, const float* __restrict__ conv_b,
                  float* __restrict__ out, int nB) {
    extern __shared__ float sm[];
    float* ps  = sm;                    // [TB][2304]
    float* xs  = sm + 18432;            // [1008][8] during conv
    float* uh  = xs;                    // [288][65]  during routing
    float* bij = sm + 18432 + 18720;    // [1152]
    float* cij = bij + 1152;            // [1152]
    float* part = cij + 1152;           // [256]
    float* sjv = part + 256;            // [64]
    float* vv  = sjv + 64;              // [64]
    float* snd = vv + 64;               // [4]

    const int tid = threadIdx.x;
    const int b0  = blockIdx.x * TB;

    // ---- load x for 8 samples, interleaved by sample for packed access ----
    for (int idx = tid; idx < TB * NPOS; idx += 256) {
        int s = idx / NPOS;
        int pos = idx - s * NPOS;
        xs[pos * TB + s] = x[(size_t)(b0 + s) * NPOS + pos];
    }
    __syncthreads();

    // ---- conv phase: thread = channel c, 36 packed accumulators (9 m x 4 sample-pairs) ----
    const int c = tid;
    unsigned long long acc[36];
    #pragma unroll
    for (int i = 0; i < 36; ++i) acc[i] = 0ull;

    const __half* ebase = g_Ehf + 256 * 256 + c;   // row tau=0
    for (int pos = 0; pos < NPOS; ++pos) {
        const float* xp = xs + pos * TB;
        unsigned long long x01 = *(const unsigned long long*)(xp + 0);
        unsigned long long x23 = *(const unsigned long long*)(xp + 2);
        unsigned long long x45 = *(const unsigned long long*)(xp + 4);
        unsigned long long x67 = *(const unsigned long long*)(xp + 6);
        const __half* ep = ebase + (size_t)pos * 256;
        #pragma unroll
        for (int m = 0; m < 9; ++m) {
            float e = __half2float(ep[-(m * 8192)]);   // row (pos-32m)+256
            unsigned long long e2 = bcast2(e);
            acc[m * 4 + 0] = ffma2(e2, x01, acc[m * 4 + 0]);
            acc[m * 4 + 1] = ffma2(e2, x23, acc[m * 4 + 1]);
            acc[m * 4 + 2] = ffma2(e2, x45, acc[m * 4 + 2]);
            acc[m * 4 + 3] = ffma2(e2, x67, acc[m * 4 + 3]);
        }
    }
    __syncthreads();   // xs region is now free (reused as uh)

    // ---- write p (+bias) to smem: ps[s][c*9+m] ----
    {
        float cb = conv_b[c];
        #pragma unroll
        for (int m = 0; m < 9; ++m) {
            #pragma unroll
            for (int sp = 0; sp < 4; ++sp) {
                float2 v = unpack2(acc[m * 4 + sp]);
                ps[(2 * sp + 0) * 2304 + c * 9 + m] = v.x + cb;
                ps[(2 * sp + 1) * 2304 + c * 9 + m] = v.y + cb;
            }
        }
    }
    __syncthreads();

    float* out_probs = out;
    float* out_cij   = out + (size_t)nB * 4;

    // ---- routing: one sample at a time ----
    for (int s = 0; s < TB; ++s) {
        float* us = ps + s * 2304;

        // squash u (in place)
        for (int j = tid; j < NCAP; j += 256) {
            float* pj = us + j * 8;
            float sn = 0.0f, v0[8];
            #pragma unroll
            for (int i = 0; i < 8; ++i) { v0[i] = pj[i]; sn += v0[i] * v0[i]; }
            float scale = (sn / (1.0f + sn)) * rsqrtf(sn + 1e-8f);
            #pragma unroll
            for (int i = 0; i < 8; ++i) pj[i] = v0[i] * scale;
        }
        __syncthreads();

        // u_hat[c,d,o] = sum_i W[c,d,o,i] * u[c,i]   (stored with stride 65)
        for (int f = tid; f < 18432; f += 256) {
            int cc = f >> 6;
            uint4 wr = *(const uint4*)(g_Whf + (size_t)f * 8);
            union { uint4 u; __half2 h[4]; } W4; W4.u = wr;
            float2 w0 = __half22float2(W4.h[0]);
            float2 w1 = __half22float2(W4.h[1]);
            float2 w2 = __half22float2(W4.h[2]);
            float2 w3 = __half22float2(W4.h[3]);
            const float* uu = us + cc * 8;
            float acc2 = w0.x * uu[0] + w0.y * uu[1] + w1.x * uu[2] + w1.y * uu[3]
                       + w2.x * uu[4] + w2.y * uu[5] + w3.x * uu[6] + w3.y * uu[7];
            uh[cc * 65 + (f & 63)] = acc2;
        }
        for (int idx = tid; idx < 1152; idx += 256) bij[idx] = 0.0f;
        __syncthreads();

        for (int r = 0; r < 3; ++r) {
            // softmax over d (4)
            for (int j = tid; j < NCAP; j += 256) {
                float b0v = bij[j * 4 + 0], b1v = bij[j * 4 + 1];
                float b2v = bij[j * 4 + 2], b3v = bij[j * 4 + 3];
                float mx = fmaxf(fmaxf(b0v, b1v), fmaxf(b2v, b3v));
                float e0 = expf(b0v - mx), e1 = expf(b1v - mx);
                float e2 = expf(b2v - mx), e3 = expf(b3v - mx);
                float inv = 1.0f / (e0 + e1 + e2 + e3);
                cij[j * 4 + 0] = e0 * inv; cij[j * 4 + 1] = e1 * inv;
                cij[j * 4 + 2] = e2 * inv; cij[j * 4 + 3] = e3 * inv;
            }
            __syncthreads();
            // s_j[d,o] = sum_c cij[c,d]*uh[c,d,o]  (4 partial sums of 72 c's)
            {
                int o64 = tid & 63, prt = tid >> 6;
                int d = o64 >> 4;
                float a2 = 0.0f;
                int cbeg = prt * 72;
                for (int cc = cbeg; cc < cbeg + 72; ++cc)
                    a2 += cij[cc * 4 + d] * uh[cc * 65 + o64];
                part[prt * 64 + o64] = a2;
            }
            __syncthreads();
            if (tid < 64)
                sjv[tid] = part[tid] + part[tid + 64] + part[tid + 128] + part[tid + 192];
            __syncthreads();
            if (tid < 4) {
                float sn = 0.0f;
                #pragma unroll
                for (int o = 0; o < 16; ++o) { float t = sjv[tid * 16 + o]; sn += t * t; }
                snd[tid] = (sn / (1.0f + sn)) * rsqrtf(sn + 1e-8f);
            }
            __syncthreads();
            if (tid < 64) vv[tid] = sjv[tid] * snd[tid >> 4];
            __syncthreads();
            if (r < 2) {
                for (int idx = tid; idx < 1152; idx += 256) {
                    int cc = idx >> 2, d2 = idx & 3;
                    const float* up = uh + cc * 65 + d2 * 16;
                    const float* vp = vv + d2 * 16;
                    float agr = 0.0f;
                    #pragma unroll
                    for (int o = 0; o < 16; ++o) agr += up[o] * vp[o];
                    bij[idx] += agr;
                }
                __syncthreads();
            }
        }

        // outputs for this sample
        int gb = b0 + s;
        if (tid < 4) {
            float sn = 0.0f;
            #pragma unroll
            for (int o = 0; o < 16; ++o) { float t = vv[tid * 16 + o]; sn += t * t; }
            out_probs[gb * 4 + tid] = sqrtf(sn);
        }
        for (int idx = tid; idx < 1152; idx += 256)
            out_cij[(size_t)gb * 1152 + idx] = cij[idx];
        __syncthreads();
    }
}

// ---------------- launcher ----------------
extern "C" void kernel_launch(void* const* d_in, const int* in_sizes, int n_in,
                              void* d_out, int out_size) {
    const float* x      = (const float*)d_in[0];
    const float* a      = (const float*)d_in[1];
    const float* w      = (const float*)d_in[2];
    const float* conv_w = (const float*)d_in[3];
    const float* conv_b = (const float*)d_in[4];
    const float* W_caps = (const float*)d_in[5];
    int nB = in_sizes[0] / NPOS;           // 4096

    cudaFuncSetAttribute(fused_kernel, cudaFuncAttributeMaxDynamicSharedMemorySize, SMEM_BYTES);

    pad_kernel<<<512, 256>>>();
    wav_kernel<<<128, 512>>>(a, w);
    compose_kernel<<<256, 256>>>(conv_w);
    wbf_kernel<<<288, 512>>>(W_caps);
    fused_kernel<<<nB / TB, 256, SMEM_BYTES>>>(x, conv_b, (float*)d_out, nB);
}

// round 4
// speedup vs baseline: 2.1152x; 2.1152x over previous
#include <cuda_runtime.h>
#include <cuda_fp16.h>
#include <mma.h>
#include <cstdint>

using namespace nvcuda;

#define NPOS  1008
#define KPAD  768
#define NCAP  288

// ---------------- device scratch ----------------
__device__ float  g_wav[128 * 512];                 // wav[o*512+k]
__device__ __half g_B_E[256 * KPAD];                // E[c][tau], zero-padded tau>=752
__device__ float  g_P2[(size_t)4096 * 2304];        // p [b][flat=c*9+m]
__device__ __half g_UH[(size_t)4096 * 18432];       // u_hat [b][cap*64 + d*16 + o]

// ---------------- precompute kernels ----------------
__global__ void wav_kernel(const float* __restrict__ a, const float* __restrict__ w) {
    int o = blockIdx.x, k = threadIdx.x;
    float av = fmaxf(a[o], 1e-5f);
    float t  = fmaf((float)k, 2.0f / 511.0f, -1.0f);
    float ts = t / av;
    g_wav[o * 512 + k] = cosf(w[o] * t) * expf(-0.5f * ts * ts);
}

__global__ void compose_kernel(const float* __restrict__ conv_w) {
    __shared__ float cw[2048];
    int c = blockIdx.x;
    for (int i = threadIdx.x; i < 2048; i += blockDim.x) cw[i] = conv_w[c * 2048 + i];
    __syncthreads();
    for (int tau = threadIdx.x; tau < KPAD; tau += blockDim.x) {
        float acc = 0.0f;
        if (tau < 752) {
            #pragma unroll
            for (int k2 = 0; k2 < 16; ++k2) {
                int k = tau - 16 * k2;
                if (k >= 0 && k < 512) {
                    const float* wr = g_wav + k;
                    #pragma unroll 8
                    for (int o = 0; o < 128; ++o)
                        acc = fmaf(cw[o * 16 + k2], wr[o * 512], acc);
                }
            }
        }
        g_B_E[c * KPAD + tau] = __float2half_rn(acc);
    }
}

// ---------------- conv GEMM (wmma): P[36864,256] = im2col(x) x E^T ----------------
// smem: As[128*72]h (18432B) | Bs[128*72]h (18432B) | bias[128]f (512B)
// epilogue reuses As+Bs as stage[128*68]f (34816B)
#define CONV_SMEM (36864 + 512)
__global__ __launch_bounds__(256, 2)
void conv_wmma_kernel(const float* __restrict__ x, const float* __restrict__ conv_b) {
    extern __shared__ char smem[];
    __half* As = (__half*)smem;
    __half* Bs = As + 128 * 72;
    float*  stage = (float*)smem;
    float*  bias  = (float*)(smem + 36864);

    const int tid = threadIdx.x;
    const int wid = tid >> 5;
    const int wm = wid & 3, wn = wid >> 2;
    const int r0 = blockIdx.x * 128;
    const int n0 = blockIdx.y * 128;

    if (tid < 128) bias[tid] = conv_b[n0 + tid];

    const int row = tid >> 1, seg = (tid & 1) * 32;
    const int r = r0 + row, ab = r / 9, am = r - 9 * ab;
    const float* xrow = x + (size_t)ab * NPOS + 32 * am;
    const __half* brow = g_B_E + (size_t)(n0 + row) * KPAD;

    wmma::fragment<wmma::matrix_a, 16, 16, 16, __half, wmma::row_major> af[2];
    wmma::fragment<wmma::matrix_b, 16, 16, 16, __half, wmma::col_major> bf[4];
    wmma::fragment<wmma::accumulator, 16, 16, 16, float> acc[2][4];
    #pragma unroll
    for (int i = 0; i < 2; ++i)
        #pragma unroll
        for (int j = 0; j < 4; ++j)
            wmma::fill_fragment(acc[i][j], 0.0f);

    for (int chunk = 0; chunk < 12; ++chunk) {
        // ---- A: 128 x 64 halves (im2col of x, fp32->fp16) ----
        {
            int kbase = chunk * 64 + seg;
            uint32_t hw[16];
            if (chunk < 11 || seg == 0) {
                const float4* xp = (const float4*)(xrow + kbase);
                #pragma unroll
                for (int q = 0; q < 8; ++q) {
                    float4 v = xp[q];
                    __half2_raw h0 = __half2_raw(__floats2half2_rn(v.x, v.y));
                    __half2_raw h1 = __half2_raw(__floats2half2_rn(v.z, v.w));
                    hw[2*q]   = h0.x | ((uint32_t)h0.y << 16);
                    hw[2*q+1] = h1.x | ((uint32_t)h1.y << 16);
                }
            } else {   // chunk 11, seg 32: tau 736..767, valid < 752
                const float4* xp = (const float4*)(xrow + kbase);
                #pragma unroll
                for (int q = 0; q < 4; ++q) {
                    float4 v = xp[q];
                    __half2_raw h0 = __half2_raw(__floats2half2_rn(v.x, v.y));
                    __half2_raw h1 = __half2_raw(__floats2half2_rn(v.z, v.w));
                    hw[2*q]   = h0.x | ((uint32_t)h0.y << 16);
                    hw[2*q+1] = h1.x | ((uint32_t)h1.y << 16);
                }
                #pragma unroll
                for (int q = 8; q < 16; ++q) hw[q] = 0u;
            }
            uint2* ap = (uint2*)(As + row * 72 + seg);
            #pragma unroll
            for (int q = 0; q < 8; ++q) ap[q] = make_uint2(hw[2*q], hw[2*q+1]);
        }
        // ---- B: 128 x 64 halves from g_B_E ----
        {
            const uint4* bp = (const uint4*)(brow + chunk * 64 + seg);
            uint2* dp = (uint2*)(Bs + row * 72 + seg);
            #pragma unroll
            for (int q = 0; q < 4; ++q) {
                uint4 v = bp[q];
                dp[2*q]   = make_uint2(v.x, v.y);
                dp[2*q+1] = make_uint2(v.z, v.w);
            }
        }
        __syncthreads();
        #pragma unroll
        for (int kk = 0; kk < 4; ++kk) {
            #pragma unroll
            for (int i = 0; i < 2; ++i)
                wmma::load_matrix_sync(af[i], As + (wm*32 + i*16) * 72 + kk*16, 72);
            #pragma unroll
            for (int j = 0; j < 4; ++j)
                wmma::load_matrix_sync(bf[j], Bs + (wn*64 + j*16) * 72 + kk*16, 72);
            #pragma unroll
            for (int i = 0; i < 2; ++i)
                #pragma unroll
                for (int j = 0; j < 4; ++j)
                    wmma::mma_sync(acc[i][j], af[i], bf[j], acc[i][j]);
        }
        __syncthreads();
    }

    // ---- epilogue: two n-half passes, stage + scatter-transpose into P2 ----
    const int b_first = r0 / 9;
    const int nb = (r0 + 127) / 9 - b_first + 1;
    for (int p = 0; p < 2; ++p) {
        if (wn == p) {
            #pragma unroll
            for (int i = 0; i < 2; ++i)
                #pragma unroll
                for (int j = 0; j < 4; ++j)
                    wmma::store_matrix_sync(stage + (wm*32 + i*16) * 68 + j*16,
                                            acc[i][j], 68, wmma::mem_row_major);
        }
        __syncthreads();
        for (int i = tid; i < nb * 64; i += 256) {
            int bl = i >> 6, col = i & 63;
            int b = b_first + bl;
            int c = n0 + p * 64 + col;
            float bv = bias[p * 64 + col];
            float* dst = g_P2 + (size_t)b * 2304 + c * 9;
            int rb = b * 9;
            #pragma unroll
            for (int m = 0; m < 9; ++m) {
                int rr = rb + m;
                if (rr >= r0 && rr < r0 + 128)
                    dst[m] = stage[(rr - r0) * 68 + col] + bv;
            }
        }
        __syncthreads();
    }
}

// ---------------- u_hat (wmma): warp-per-capsule batched GEMM ----------------
// smem: Bw 8x(64x16)h = 16384B | Aw 8x(32x16)h = 8192B | stg 8x(16x64)f = 32768B
#define UHAT_SMEM (16384 + 8192 + 32768)
__global__ __launch_bounds__(256, 2)
void uhat_wmma_kernel(const float* __restrict__ Wc) {
    extern __shared__ char smem[];
    const int tid = threadIdx.x, wid = tid >> 5, lane = tid & 31;
    __half* Bw = (__half*)smem + wid * 1024;              // [64][16]
    __half* Aw = (__half*)(smem + 16384) + wid * 512;     // [32][16]
    float*  stg = (float*)(smem + 24576) + wid * 1024;    // [16][64]

    const int b0 = blockIdx.x * 128;
    const int c  = blockIdx.y * 8 + wid;                  // capsule 0..287

    // load W_c -> Bw (col-major [k][n]: element (k,n) at n*16+k), pad k>=8 with 0
    {
        const float4* wp = (const float4*)(Wc + (size_t)c * 512);
        #pragma unroll
        for (int t = 0; t < 2; ++t) {
            int n = lane * 2 + t;
            float4 v0 = wp[n * 2], v1 = wp[n * 2 + 1];
            __half2_raw h0 = __half2_raw(__floats2half2_rn(v0.x, v0.y));
            __half2_raw h1 = __half2_raw(__floats2half2_rn(v0.z, v0.w));
            __half2_raw h2 = __half2_raw(__floats2half2_rn(v1.x, v1.y));
            __half2_raw h3 = __half2_raw(__floats2half2_rn(v1.z, v1.w));
            uint4* dp = (uint4*)(Bw + n * 16);
            dp[0] = make_uint4(h0.x | ((uint32_t)h0.y << 16), h1.x | ((uint32_t)h1.y << 16),
                               h2.x | ((uint32_t)h2.y << 16), h3.x | ((uint32_t)h3.y << 16));
            dp[1] = make_uint4(0u, 0u, 0u, 0u);
        }
    }
    __syncwarp();

    wmma::fragment<wmma::matrix_b, 16, 16, 16, __half, wmma::col_major> bf[4];
    #pragma unroll
    for (int j = 0; j < 4; ++j)
        wmma::load_matrix_sync(bf[j], Bw + j * 16 * 16, 16);

    for (int mblk = 0; mblk < 4; ++mblk) {
        // squash u for 32 b's of this capsule -> Aw rows (k padded to 16)
        {
            int b = b0 + mblk * 32 + lane;
            const float4* pp = (const float4*)(g_P2 + (size_t)b * 2304 + c * 8);
            float4 p0 = pp[0], p1 = pp[1];
            float sn = p0.x*p0.x + p0.y*p0.y + p0.z*p0.z + p0.w*p0.w
                     + p1.x*p1.x + p1.y*p1.y + p1.z*p1.z + p1.w*p1.w;
            float sc = (sn / (1.0f + sn)) * rsqrtf(sn + 1e-8f);
            __half2_raw h0 = __half2_raw(__floats2half2_rn(p0.x*sc, p0.y*sc));
            __half2_raw h1 = __half2_raw(__floats2half2_rn(p0.z*sc, p0.w*sc));
            __half2_raw h2 = __half2_raw(__floats2half2_rn(p1.x*sc, p1.y*sc));
            __half2_raw h3 = __half2_raw(__floats2half2_rn(p1.z*sc, p1.w*sc));
            uint4* dp = (uint4*)(Aw + lane * 16);
            dp[0] = make_uint4(h0.x | ((uint32_t)h0.y << 16), h1.x | ((uint32_t)h1.y << 16),
                               h2.x | ((uint32_t)h2.y << 16), h3.x | ((uint32_t)h3.y << 16));
            dp[1] = make_uint4(0u, 0u, 0u, 0u);
        }
        __syncwarp();

        #pragma unroll
        for (int i = 0; i < 2; ++i) {
            wmma::fragment<wmma::matrix_a, 16, 16, 16, __half, wmma::row_major> af;
            wmma::load_matrix_sync(af, Aw + i * 16 * 16, 16);
            wmma::fragment<wmma::accumulator, 16, 16, 16, float> acc[4];
            #pragma unroll
            for (int j = 0; j < 4; ++j) {
                wmma::fill_fragment(acc[j], 0.0f);
                wmma::mma_sync(acc[j], af, bf[j], acc[j]);
                wmma::store_matrix_sync(stg + j * 16, acc[j], 64, wmma::mem_row_major);
            }
            __syncwarp();
            // write 16 rows x 64 cols fp16 to g_UH
            {
                int rrow = lane >> 1, cseg = (lane & 1) * 32;
                int b = b0 + mblk * 32 + i * 16 + rrow;
                const float* sp = stg + rrow * 64 + cseg;
                uint4 ov[2];
                #pragma unroll
                for (int u = 0; u < 2; ++u) {
                    uint32_t pk[4];
                    #pragma unroll
                    for (int e = 0; e < 4; ++e) {
                        __half2_raw h = __half2_raw(__floats2half2_rn(sp[u*16 + 4*e],
                                                                      sp[u*16 + 4*e + 1]));
                        __half2_raw g = __half2_raw(__floats2half2_rn(sp[u*16 + 4*e + 2],
                                                                      sp[u*16 + 4*e + 3]));
                        pk[e] = 0;
                        pk[e] = h.x | ((uint32_t)h.y << 16);
                        // pack 4 halves into 2 words per e -> build directly:
                        (void)g;
                    }
                    // rebuild properly below
                    ov[u] = make_uint4(0,0,0,0);
                }
                // straightforward scalar-pair packing (8 half2 per 16 floats)
                __half2* dst = (__half2*)(g_UH + (size_t)b * 18432 + c * 64 + cseg);
                #pragma unroll
                for (int e = 0; e < 16; ++e)
                    dst[e] = __floats2half2_rn(sp[2*e], sp[2*e + 1]);
                (void)ov;
            }
            __syncwarp();
        }
    }
}

// ---------------- routing: 1 sample per CTA ----------------
#define ROUT_FLOATS (18720 + 1152 + 1152 + 256 + 64 + 64 + 4)
#define ROUT_SMEM   (ROUT_FLOATS * 4)
__global__ __launch_bounds__(256, 2)
void routing_kernel(float* __restrict__ out, int nB) {
    extern __shared__ float sm[];
    float* uh   = sm;              // [288][65]
    float* bij  = sm + 18720;
    float* cij  = bij + 1152;
    float* part = cij + 1152;
    float* sjv  = part + 256;
    float* vv   = sjv + 64;
    float* snd  = vv + 64;
    const int tid = threadIdx.x;
    const int b = blockIdx.x;

    const uint4* src = (const uint4*)(g_UH + (size_t)b * 18432);
    #pragma unroll
    for (int it = 0; it < 9; ++it) {
        int vi = tid + it * 256;
        uint4 v = src[vi];
        int cc = vi >> 3, o0 = (vi & 7) * 8;
        float* d = uh + cc * 65 + o0;
        __half2* h = (__half2*)&v;
        #pragma unroll
        for (int e = 0; e < 4; ++e) {
            float2 f = __half22float2(h[e]);
            d[2*e] = f.x; d[2*e+1] = f.y;
        }
    }
    for (int i = tid; i < 1152; i += 256) bij[i] = 0.0f;
    __syncthreads();

    for (int r = 0; r < 3; ++r) {
        for (int j = tid; j < NCAP; j += 256) {
            float b0 = bij[j*4+0], b1 = bij[j*4+1], b2 = bij[j*4+2], b3 = bij[j*4+3];
            float mx = fmaxf(fmaxf(b0, b1), fmaxf(b2, b3));
            float e0 = expf(b0-mx), e1 = expf(b1-mx), e2 = expf(b2-mx), e3 = expf(b3-mx);
            float inv = 1.0f / (e0 + e1 + e2 + e3);
            cij[j*4+0] = e0*inv; cij[j*4+1] = e1*inv; cij[j*4+2] = e2*inv; cij[j*4+3] = e3*inv;
        }
        __syncthreads();
        {
            int o64 = tid & 63, prt = tid >> 6, d = o64 >> 4;
            float a2 = 0.0f;
            int cb = prt * 72;
            for (int cc = cb; cc < cb + 72; ++cc)
                a2 += cij[cc * 4 + d] * uh[cc * 65 + o64];
            part[prt * 64 + o64] = a2;
        }
        __syncthreads();
        if (tid < 64)
            sjv[tid] = part[tid] + part[tid+64] + part[tid+128] + part[tid+192];
        __syncthreads();
        if (tid < 4) {
            float sn = 0.0f;
            #pragma unroll
            for (int o = 0; o < 16; ++o) { float t = sjv[tid*16+o]; sn += t*t; }
            snd[tid] = (sn / (1.0f + sn)) * rsqrtf(sn + 1e-8f);
        }
        __syncthreads();
        if (tid < 64) vv[tid] = sjv[tid] * snd[tid >> 4];
        __syncthreads();
        if (r < 2) {
            for (int i = tid; i < 1152; i += 256) {
                int cc = i >> 2, d2 = i & 3;
                const float* up = uh + cc * 65 + d2 * 16;
                const float* vp = vv + d2 * 16;
                float agr = 0.0f;
                #pragma unroll
                for (int o = 0; o < 16; ++o) agr += up[o] * vp[o];
                bij[i] += agr;
            }
            __syncthreads();
        }
    }
    if (tid < 4) {
        float sn = 0.0f;
        #pragma unroll
        for (int o = 0; o < 16; ++o) { float t = vv[tid*16+o]; sn += t*t; }
        out[b * 4 + tid] = sqrtf(sn);
    }
    float* out_cij = out + (size_t)nB * 4 + (size_t)b * 1152;
    for (int i = tid; i < 1152; i += 256) out_cij[i] = cij[i];
}

// ---------------- launcher ----------------
extern "C" void kernel_launch(void* const* d_in, const int* in_sizes, int n_in,
                              void* d_out, int out_size) {
    const float* x      = (const float*)d_in[0];
    const float* a      = (const float*)d_in[1];
    const float* w      = (const float*)d_in[2];
    const float* conv_w = (const float*)d_in[3];
    const float* conv_b = (const float*)d_in[4];
    const float* W_caps = (const float*)d_in[5];
    int nB = in_sizes[0] / NPOS;   // 4096

    cudaFuncSetAttribute(uhat_wmma_kernel, cudaFuncAttributeMaxDynamicSharedMemorySize, UHAT_SMEM);
    cudaFuncSetAttribute(routing_kernel,   cudaFuncAttributeMaxDynamicSharedMemorySize, ROUT_SMEM);

    wav_kernel<<<128, 512>>>(a, w);
    compose_kernel<<<256, 256>>>(conv_w);
    conv_wmma_kernel<<<dim3(nB * 9 / 128, 2), 256, CONV_SMEM>>>(x, conv_b);
    uhat_wmma_kernel<<<dim3(nB / 128, 36), 256, UHAT_SMEM>>>(W_caps);
    routing_kernel<<<nB, 256, ROUT_SMEM>>>((float*)d_out, nB);
}